// round 11
// baseline (speedup 1.0000x reference)
#include <cuda_runtime.h>
#include <math.h>
#include <stdint.h>

// PA-MPJPE: Horn quaternion + QUEST Newton eigenvalue + adjugate eigenvector.
// Persistent CTAs, per-warp double-buffered cp.async pipeline.
// R9: instruction surgery — scale = lambda/var1 (Horn identity), adjugate via
// shared 2x2 minors, unnormalized-quaternion rotation, Newton 5 iters.

constexpr int J     = 14;
constexpr int FPE   = J * 3;               // 42 floats per element
constexpr int EPW   = 28;                  // elements per warp
constexpr int WARPS = 4;
constexpr int TPB   = WARPS * 32;          // 128
constexpr int EPT   = WARPS * EPW;         // 112 elements per CTA-tile
constexpr int WB_ARR = EPW * FPE * 4;      // 4704 B per array per warp
constexpr int WV4_FULL = (WB_ARR / 16);    // 294 float4 per array per warp
constexpr int WBYTES = 2 * WB_ARR;         // 9408 B per warp (pred+gt)
constexpr int TILE_BYTES = WARPS * WBYTES; // 37632 B
constexpr int SMEM_BYTES = 2 * TILE_BYTES; // 75264 B (double buffer)
constexpr int GRID  = 456;                 // 3 CTAs/SM x 152 SMs (GB300)

__device__ __forceinline__ uint32_t smem_u32(const void* p) {
    uint32_t a;
    asm("{ .reg .u64 t; cvta.to.shared.u64 t, %1; cvt.u32.u64 %0, t; }"
        : "=r"(a) : "l"(p));
    return a;
}

__device__ __forceinline__ void cp16(uint32_t s, const void* g) {
    asm volatile("cp.async.cg.shared.global [%0], [%1], 16;"
                 :: "r"(s), "l"(g) : "memory");
}
__device__ __forceinline__ void cp4(uint32_t s, const void* g) {
    asm volatile("cp.async.ca.shared.global [%0], [%1], 4;"
                 :: "r"(s), "l"(g) : "memory");
}
__device__ __forceinline__ void cp_commit() {
    asm volatile("cp.async.commit_group;" ::: "memory");
}
template<int N>
__device__ __forceinline__ void cp_wait() {
    asm volatile("cp.async.wait_group %0;" :: "n"(N) : "memory");
}

// Prefetch this warp's EPW-element slice of a tile into its shared region.
__device__ __forceinline__ void prefetch_slice(uint32_t sbase,
                                               const float* __restrict__ pred,
                                               const float* __restrict__ gt,
                                               long long fbase, long long total,
                                               int lane)
{
    if (fbase + EPW * FPE <= total) {
        const char* gp = (const char*)(pred + fbase);
        const char* gg = (const char*)(gt   + fbase);
        #pragma unroll
        for (int i = 0; i < 9; i++) {          // 9*32 = 288 float4
            int o = (lane + 32 * i) * 16;
            cp16(sbase + o,          gp + o);
            cp16(sbase + WB_ARR + o, gg + o);
        }
        if (lane < WV4_FULL - 288) {           // tail: 6 float4
            int o = (288 + lane) * 16;
            cp16(sbase + o,          gp + o);
            cp16(sbase + WB_ARR + o, gg + o);
        }
    } else if (fbase < total) {
        int rem = (int)(total - fbase);
        for (int idx = lane; idx < rem; idx += 32) {
            cp4(sbase + idx * 4,          (const void*)(pred + fbase + idx));
            cp4(sbase + WB_ARR + idx * 4, (const void*)(gt   + fbase + idx));
        }
    }
}

__device__ __forceinline__ float compute_elem(const float* __restrict__ pw,
                                              const float* __restrict__ gw,
                                              int lane)
{
    const float2* P2 = reinterpret_cast<const float2*>(pw + lane * FPE);
    const float2* G2 = reinterpret_cast<const float2*>(gw + lane * FPE);

    // ---- pass 1: sums, |a|^2, cross-covariance S = sum a b^T ----
    float sax = 0.f, say = 0.f, saz = 0.f;
    float sbx = 0.f, sby = 0.f, sbz = 0.f;
    float saa = 0.f;
    float S00 = 0.f, S01 = 0.f, S02 = 0.f;
    float S10 = 0.f, S11 = 0.f, S12 = 0.f;
    float S20 = 0.f, S21 = 0.f, S22 = 0.f;
    #pragma unroll
    for (int c = 0; c < 7; c++) {
        float2 a0 = P2[3*c], a1 = P2[3*c+1], a2 = P2[3*c+2];
        float2 b0 = G2[3*c], b1 = G2[3*c+1], b2 = G2[3*c+2];
        {
            float ax = a0.x, ay = a0.y, az = a1.x;
            float bx = b0.x, by = b0.y, bz = b1.x;
            sax += ax; say += ay; saz += az;
            sbx += bx; sby += by; sbz += bz;
            saa += ax*ax + ay*ay + az*az;
            S00 += ax*bx; S01 += ax*by; S02 += ax*bz;
            S10 += ay*bx; S11 += ay*by; S12 += ay*bz;
            S20 += az*bx; S21 += az*by; S22 += az*bz;
        }
        {
            float ax = a1.y, ay = a2.x, az = a2.y;
            float bx = b1.y, by = b2.x, bz = b2.y;
            sax += ax; say += ay; saz += az;
            sbx += bx; sby += by; sbz += bz;
            saa += ax*ax + ay*ay + az*az;
            S00 += ax*bx; S01 += ax*by; S02 += ax*bz;
            S10 += ay*bx; S11 += ay*by; S12 += ay*bz;
            S20 += az*bx; S21 += az*by; S22 += az*bz;
        }
    }
    const float invJ = 1.0f / (float)J;
    const float max_ = sax*invJ, may_ = say*invJ, maz_ = saz*invJ;
    const float mbx  = sbx*invJ, mby  = sby*invJ, mbz  = sbz*invJ;

    // centered covariance K (dies after N is built) and var1
    const float K00 = S00 - sax*mbx, K01 = S01 - sax*mby, K02 = S02 - sax*mbz;
    const float K10 = S10 - say*mbx, K11 = S11 - say*mby, K12 = S12 - say*mbz;
    const float K20 = S20 - saz*mbx, K21 = S21 - saz*mby, K22 = S22 - saz*mbz;
    const float var1 = saa - (sax*max_ + say*may_ + saz*maz_);

    // ---- Horn's symmetric traceless 4x4 N ----
    const float n00 =  K00 + K11 + K22;
    const float n01 =  K12 - K21;
    const float n02 =  K20 - K02;
    const float n03 =  K01 - K10;
    const float n11 =  K00 - K11 - K22;
    const float n12 =  K01 + K10;
    const float n13 =  K20 + K02;
    const float n22 = -K00 + K11 - K22;
    const float n23 =  K12 + K21;
    const float n33 = -K00 - K11 + K22;

    // ---- characteristic quartic via power traces (trace N = 0) ----
    const float t00 = n00*n00 + n01*n01 + n02*n02 + n03*n03;
    const float t01 = n00*n01 + n01*n11 + n02*n12 + n03*n13;
    const float t02 = n00*n02 + n01*n12 + n02*n22 + n03*n23;
    const float t03 = n00*n03 + n01*n13 + n02*n23 + n03*n33;
    const float t11 = n01*n01 + n11*n11 + n12*n12 + n13*n13;
    const float t12 = n01*n02 + n11*n12 + n12*n22 + n13*n23;
    const float t13 = n01*n03 + n11*n13 + n12*n23 + n13*n33;
    const float t22 = n02*n02 + n12*n12 + n22*n22 + n23*n23;
    const float t23 = n02*n03 + n12*n13 + n22*n23 + n23*n33;
    const float t33 = n03*n03 + n13*n13 + n23*n23 + n33*n33;

    const float p2 = t00 + t11 + t22 + t33;
    const float p3 = n00*t00 + n11*t11 + n22*t22 + n33*t33
                   + 2.f*(n01*t01 + n02*t02 + n03*t03
                        + n12*t12 + n13*t13 + n23*t23);
    const float p4 = t00*t00 + t11*t11 + t22*t22 + t33*t33
                   + 2.f*(t01*t01 + t02*t02 + t03*t03
                        + t12*t12 + t13*t13 + t23*t23);

    const float c2 = -0.5f * p2;
    const float c1 = -(1.0f/3.0f) * p3;
    const float c0 = 0.125f * p2 * p2 - 0.25f * p4;

    // Newton from upper bound sqrt(3/4 * p2) >= lambda_max (monotone)
    float lam = 0.75f * p2;
    lam = lam * rsqrtf(fmaxf(lam, 1e-30f));
    #pragma unroll
    for (int it = 0; it < 5; it++) {
        float lam2 = lam * lam;
        float f  = ((lam2 + c2) * lam + c1) * lam + c0;
        float fp = (4.f * lam2 + 2.f * c2) * lam + c1;
        lam -= __fdividef(f, fmaxf(fp, 1e-20f));
    }

    // ---- eigenvector = column of adj(M), M = N - lam I (rank-3, sym) ----
    // shared 2x2-minor scheme (glm/Lengyel); adj(M) = mu * q q^T
    const float m00 = n00 - lam, m11 = n11 - lam;
    const float m22 = n22 - lam, m33 = n33 - lam;

    const float s0 = m00*m11 - n01*n01;
    const float s1 = m00*n12 - n01*n02;
    const float s2 = m00*n13 - n01*n03;
    const float s3 = n01*n12 - m11*n02;
    const float s4 = n01*n13 - m11*n03;
    const float s5 = n02*n13 - n12*n03;
    const float c5_ = m22*m33 - n23*n23;
    const float c4_ = n12*m33 - n13*n23;
    const float c3_ = n12*n23 - n13*m22;
    const float c2_ = n02*m33 - n03*n23;
    const float c1_ = n02*n23 - n03*m22;
    const float c0_ = n02*n13 - n03*n12;

    const float b00 =  m11*c5_ - n12*c4_ + n13*c3_;
    const float b01 = -n01*c5_ + n02*c4_ - n03*c3_;
    const float b02 =  n13*s5  - n23*s4  + m33*s3;
    const float b03 = -n12*s5  + m22*s4  - n23*s3;
    const float b11 =  m00*c5_ - n02*c2_ + n03*c1_;
    const float b12 = -n03*s5  + n23*s2  - m33*s1;
    const float b13 =  n02*s5  - m22*s2  + n23*s1;
    const float b22 =  n03*s4  - n13*s2  + m33*s0;
    const float b23 = -n02*s4  + n12*s2  - n23*s0;
    const float b33 =  n02*s3  - n12*s1  + m22*s0;

    float best = fabsf(b00);
    float qw = b00, qx = b01, qy = b02, qz = b03;
    if (fabsf(b11) > best) { best = fabsf(b11); qw = b01; qx = b11; qy = b12; qz = b13; }
    if (fabsf(b22) > best) { best = fabsf(b22); qw = b02; qx = b12; qy = b22; qz = b23; }
    if (fabsf(b33) > best) { best = fabsf(b33); qw = b03; qx = b13; qy = b23; qz = b33; }

    // ---- unnormalized quaternion -> M = k * Rn, k = lam/(var1*|q|^2) ----
    // (Horn identity: trace(R K) = lam_max, so scale = lam/var1)
    const float xx = qx*qx, yy = qy*qy, zz = qz*qz, ww = qw*qw;
    const float q2 = ww + xx + yy + zz;
    const float xy = qx*qy, xz = qx*qz, yz = qy*qz;
    const float wx = qw*qx, wy = qw*qy, wz = qw*qz;

    const float k  = __fdividef(lam, var1 * q2);
    const float k2 = 2.f * k;
    const float M00 = k*(ww + xx - yy - zz), M01 = k2*(xy - wz), M02 = k2*(xz + wy);
    const float M10 = k2*(xy + wz), M11 = k*(ww - xx + yy - zz), M12 = k2*(yz - wx);
    const float M20 = k2*(xz - wy), M21 = k2*(yz + wx), M22 = k*(ww - xx - yy + zz);

    // fold translation: r_j = (M a_j + c) - b_j,  c = mu_b - M mu_a
    const float cx = mbx - (M00*max_ + M01*may_ + M02*maz_);
    const float cy = mby - (M10*max_ + M11*may_ + M12*maz_);
    const float cz = mbz - (M20*max_ + M21*may_ + M22*maz_);

    float acc = 0.f;
    #pragma unroll
    for (int c = 0; c < 7; c++) {
        float2 a0 = P2[3*c], a1 = P2[3*c+1], a2 = P2[3*c+2];
        float2 b0 = G2[3*c], b1 = G2[3*c+1], b2 = G2[3*c+2];
        {
            float ax = a0.x, ay = a0.y, az = a1.x;
            float ex = (M00*ax + M01*ay + M02*az + cx) - b0.x;
            float ey = (M10*ax + M11*ay + M12*az + cy) - b0.y;
            float ez = (M20*ax + M21*ay + M22*az + cz) - b1.x;
            float d2 = ex*ex + ey*ey + ez*ez;
            acc += d2 * rsqrtf(fmaxf(d2, 1e-24f));
        }
        {
            float ax = a1.y, ay = a2.x, az = a2.y;
            float ex = (M00*ax + M01*ay + M02*az + cx) - b1.y;
            float ey = (M10*ax + M11*ay + M12*az + cy) - b2.x;
            float ez = (M20*ax + M21*ay + M22*az + cz) - b2.y;
            float d2 = ex*ex + ey*ey + ez*ez;
            acc += d2 * rsqrtf(fmaxf(d2, 1e-24f));
        }
    }
    return acc * invJ;
}

__global__ void __launch_bounds__(TPB, 3)
pampjpe_kernel(const float* __restrict__ pred,
               const float* __restrict__ gt,
               float* __restrict__ out, int B)
{
    extern __shared__ float smem[];
    const int tid  = threadIdx.x;
    const int warp = tid >> 5;
    const int lane = tid & 31;
    const long long total = (long long)B * FPE;
    const int ntiles = (B + EPT - 1) / EPT;

    // this warp's region in each of the two buffers
    const uint32_t w0 = smem_u32(smem) + warp * WBYTES;
    const uint32_t wreg0 = w0;
    const uint32_t wreg1 = w0 + (uint32_t)TILE_BYTES;
    const float* wptr0 = smem + (warp * WBYTES) / 4;
    const float* wptr1 = smem + (TILE_BYTES + warp * WBYTES) / 4;

    int tile = blockIdx.x;
    if (tile >= ntiles) return;

    // prime the pipeline
    {
        long long fbase = ((long long)tile * EPT + warp * EPW) * FPE;
        prefetch_slice(wreg0, pred, gt, fbase, total, lane);
        cp_commit();
    }

    int buf = 0;
    for (; tile < ntiles; tile += GRID) {
        int next = tile + GRID;
        if (next < ntiles) {
            long long fn = ((long long)next * EPT + warp * EPW) * FPE;
            prefetch_slice(buf ? wreg0 : wreg1, pred, gt, fn, total, lane);
            cp_commit();
            cp_wait<1>();
        } else {
            cp_wait<0>();
        }
        __syncwarp();

        long long elem = (long long)tile * EPT + warp * EPW + lane;
        if (lane < EPW && elem < B) {
            const float* pw = buf ? wptr1 : wptr0;
            const float* gw = pw + WB_ARR / 4;
            out[elem] = compute_elem(pw, gw, lane);
        }
        __syncwarp();   // all lanes done reading before next overwrite
        buf ^= 1;
    }
}

extern "C" void kernel_launch(void* const* d_in, const int* in_sizes, int n_in,
                              void* d_out, int out_size)
{
    const float* pred = (const float*)d_in[0];
    const float* gt   = (const float*)d_in[1];
    float* out = (float*)d_out;
    const int B = out_size;
    const int ntiles = (B + EPT - 1) / EPT;
    const int grid = GRID < ntiles ? GRID : ntiles;

    static bool attr_set = false;
    if (!attr_set) {
        cudaFuncSetAttribute(pampjpe_kernel,
                             cudaFuncAttributeMaxDynamicSharedMemorySize,
                             SMEM_BYTES);
        attr_set = true;
    }
    pampjpe_kernel<<<grid, TPB, SMEM_BYTES>>>(pred, gt, out, B);
}

// round 12
// speedup vs baseline: 1.0336x; 1.0336x over previous
#include <cuda_runtime.h>
#include <math.h>
#include <stdint.h>

// PA-MPJPE: Horn quaternion + QUEST Newton eigenvalue + adjugate eigenvector.
// Persistent CTAs, per-warp double-buffered pipeline.
// R12: cp.async (294 x 8cyc LDGSTS issue per warp-tile == the measured wall)
// replaced by cp.async.bulk + mbarrier (2 bulk ops per warp-tile).

constexpr int J     = 14;
constexpr int FPE   = J * 3;               // 42 floats per element
constexpr int EPW   = 28;                  // elements per warp
constexpr int WARPS = 4;
constexpr int TPB   = WARPS * 32;          // 128
constexpr int EPT   = WARPS * EPW;         // 112 elements per CTA-tile
constexpr int WF    = EPW * FPE;           // 1176 floats per array per warp
constexpr int WB_ARR = WF * 4;             // 4704 B per array per warp
constexpr int WBYTES = 2 * WB_ARR;         // 9408 B per warp (pred+gt)
constexpr int TILE_BYTES = WARPS * WBYTES; // 37632 B
constexpr int DATA_BYTES = 2 * TILE_BYTES; // 75264 B (double buffer)
constexpr int MBAR_BYTES = WARPS * 2 * 8;  // 8 mbarriers (warp x buffer)
constexpr int SMEM_BYTES = DATA_BYTES + MBAR_BYTES;
constexpr int GRID  = 456;                 // 3 CTAs/SM x 152 SMs (GB300)

__device__ __forceinline__ uint32_t smem_u32(const void* p) {
    uint32_t a;
    asm("{ .reg .u64 t; cvta.to.shared.u64 t, %1; cvt.u32.u64 %0, t; }"
        : "=r"(a) : "l"(p));
    return a;
}

__device__ __forceinline__ void mbar_init(uint32_t mbar, uint32_t count) {
    asm volatile("mbarrier.init.shared.b64 [%0], %1;"
                 :: "r"(mbar), "r"(count) : "memory");
}
__device__ __forceinline__ void mbar_expect_tx(uint32_t mbar, uint32_t bytes) {
    asm volatile("mbarrier.arrive.expect_tx.shared.b64 _, [%0], %1;"
                 :: "r"(mbar), "r"(bytes) : "memory");
}
__device__ __forceinline__ void mbar_wait(uint32_t mbar, uint32_t parity) {
    uint32_t done;
    asm volatile(
        "{\n\t.reg .pred p;\n\t"
        "mbarrier.try_wait.parity.acquire.cta.shared::cta.b64 p, [%1], %2;\n\t"
        "selp.b32 %0, 1, 0, p;\n\t}"
        : "=r"(done) : "r"(mbar), "r"(parity) : "memory");
    if (!done) {
        asm volatile(
            "{\n\t.reg .pred P1;\n\t"
            "WAIT_LOOP_%=:\n\t"
            "mbarrier.try_wait.parity.acquire.cta.shared::cta.b64 P1, [%0], %1, 0x989680;\n\t"
            "@P1 bra.uni WAIT_DONE_%=;\n\t"
            "bra.uni WAIT_LOOP_%=;\n\t"
            "WAIT_DONE_%=:\n\t}"
            :: "r"(mbar), "r"(parity) : "memory");
    }
}
__device__ __forceinline__ void bulk_cp(uint32_t dst, const void* src,
                                        uint32_t bytes, uint32_t mbar) {
    asm volatile(
        "cp.async.bulk.shared::cta.global.mbarrier::complete_tx::bytes "
        "[%0], [%1], %2, [%3];"
        :: "r"(dst), "l"(src), "r"(bytes), "r"(mbar) : "memory");
}
__device__ __forceinline__ void cp4(uint32_t s, const void* g) {
    asm volatile("cp.async.ca.shared.global [%0], [%1], 4;"
                 :: "r"(s), "l"(g) : "memory");
}
__device__ __forceinline__ void cp_commit() {
    asm volatile("cp.async.commit_group;" ::: "memory");
}
__device__ __forceinline__ void cp_wait0() {
    asm volatile("cp.async.wait_group 0;" ::: "memory");
}

// Issue async fill of this warp's slice (lane 0 only). Returns nothing;
// the slice shape is recomputed identically at consume time.
__device__ __forceinline__ void prefetch_slice(uint32_t sbase, uint32_t mbar,
                                               const float* __restrict__ pred,
                                               const float* __restrict__ gt,
                                               long long fbase, long long total,
                                               int lane)
{
    if (lane != 0) return;
    if (fbase + WF <= total) {
        mbar_expect_tx(mbar, 2 * WB_ARR);
        bulk_cp(sbase,          pred + fbase, WB_ARR, mbar);
        bulk_cp(sbase + WB_ARR, gt   + fbase, WB_ARR, mbar);
    } else if (fbase < total) {
        uint32_t rem_bytes = (uint32_t)(total - fbase) * 4u;
        uint32_t b16 = rem_bytes & ~15u;
        if (b16) {
            mbar_expect_tx(mbar, 2 * b16);
            bulk_cp(sbase,          pred + fbase, b16, mbar);
            bulk_cp(sbase + WB_ARR, gt   + fbase, b16, mbar);
        }
        for (uint32_t o = b16; o < rem_bytes; o += 4) {
            cp4(sbase + o,          (const char*)pred + fbase * 4 + o);
            cp4(sbase + WB_ARR + o, (const char*)gt   + fbase * 4 + o);
        }
        cp_commit();
    }
}

__device__ __forceinline__ float compute_elem(const float* __restrict__ pw,
                                              const float* __restrict__ gw,
                                              int lane)
{
    const float2* P2 = reinterpret_cast<const float2*>(pw + lane * FPE);
    const float2* G2 = reinterpret_cast<const float2*>(gw + lane * FPE);

    // ---- pass 1: sums, |a|^2, cross-covariance S = sum a b^T ----
    float sax = 0.f, say = 0.f, saz = 0.f;
    float sbx = 0.f, sby = 0.f, sbz = 0.f;
    float saa = 0.f;
    float S00 = 0.f, S01 = 0.f, S02 = 0.f;
    float S10 = 0.f, S11 = 0.f, S12 = 0.f;
    float S20 = 0.f, S21 = 0.f, S22 = 0.f;
    #pragma unroll
    for (int c = 0; c < 7; c++) {
        float2 a0 = P2[3*c], a1 = P2[3*c+1], a2 = P2[3*c+2];
        float2 b0 = G2[3*c], b1 = G2[3*c+1], b2 = G2[3*c+2];
        {
            float ax = a0.x, ay = a0.y, az = a1.x;
            float bx = b0.x, by = b0.y, bz = b1.x;
            sax += ax; say += ay; saz += az;
            sbx += bx; sby += by; sbz += bz;
            saa += ax*ax + ay*ay + az*az;
            S00 += ax*bx; S01 += ax*by; S02 += ax*bz;
            S10 += ay*bx; S11 += ay*by; S12 += ay*bz;
            S20 += az*bx; S21 += az*by; S22 += az*bz;
        }
        {
            float ax = a1.y, ay = a2.x, az = a2.y;
            float bx = b1.y, by = b2.x, bz = b2.y;
            sax += ax; say += ay; saz += az;
            sbx += bx; sby += by; sbz += bz;
            saa += ax*ax + ay*ay + az*az;
            S00 += ax*bx; S01 += ax*by; S02 += ax*bz;
            S10 += ay*bx; S11 += ay*by; S12 += ay*bz;
            S20 += az*bx; S21 += az*by; S22 += az*bz;
        }
    }
    const float invJ = 1.0f / (float)J;
    const float max_ = sax*invJ, may_ = say*invJ, maz_ = saz*invJ;
    const float mbx  = sbx*invJ, mby  = sby*invJ, mbz  = sbz*invJ;

    const float K00 = S00 - sax*mbx, K01 = S01 - sax*mby, K02 = S02 - sax*mbz;
    const float K10 = S10 - say*mbx, K11 = S11 - say*mby, K12 = S12 - say*mbz;
    const float K20 = S20 - saz*mbx, K21 = S21 - saz*mby, K22 = S22 - saz*mbz;
    const float var1 = saa - (sax*max_ + say*may_ + saz*maz_);

    // ---- Horn's symmetric traceless 4x4 N ----
    const float n00 =  K00 + K11 + K22;
    const float n01 =  K12 - K21;
    const float n02 =  K20 - K02;
    const float n03 =  K01 - K10;
    const float n11 =  K00 - K11 - K22;
    const float n12 =  K01 + K10;
    const float n13 =  K20 + K02;
    const float n22 = -K00 + K11 - K22;
    const float n23 =  K12 + K21;
    const float n33 = -K00 - K11 + K22;

    // ---- characteristic quartic via power traces (trace N = 0) ----
    const float t00 = n00*n00 + n01*n01 + n02*n02 + n03*n03;
    const float t01 = n00*n01 + n01*n11 + n02*n12 + n03*n13;
    const float t02 = n00*n02 + n01*n12 + n02*n22 + n03*n23;
    const float t03 = n00*n03 + n01*n13 + n02*n23 + n03*n33;
    const float t11 = n01*n01 + n11*n11 + n12*n12 + n13*n13;
    const float t12 = n01*n02 + n11*n12 + n12*n22 + n13*n23;
    const float t13 = n01*n03 + n11*n13 + n12*n23 + n13*n33;
    const float t22 = n02*n02 + n12*n12 + n22*n22 + n23*n23;
    const float t23 = n02*n03 + n12*n13 + n22*n23 + n23*n33;
    const float t33 = n03*n03 + n13*n13 + n23*n23 + n33*n33;

    const float p2 = t00 + t11 + t22 + t33;
    const float p3 = n00*t00 + n11*t11 + n22*t22 + n33*t33
                   + 2.f*(n01*t01 + n02*t02 + n03*t03
                        + n12*t12 + n13*t13 + n23*t23);
    const float p4 = t00*t00 + t11*t11 + t22*t22 + t33*t33
                   + 2.f*(t01*t01 + t02*t02 + t03*t03
                        + t12*t12 + t13*t13 + t23*t23);

    const float c2 = -0.5f * p2;
    const float c1 = -(1.0f/3.0f) * p3;
    const float c0 = 0.125f * p2 * p2 - 0.25f * p4;

    // Newton from upper bound sqrt(3/4 * p2) >= lambda_max (monotone)
    float lam = 0.75f * p2;
    lam = lam * rsqrtf(fmaxf(lam, 1e-30f));
    #pragma unroll
    for (int it = 0; it < 6; it++) {
        float lam2 = lam * lam;
        float f  = ((lam2 + c2) * lam + c1) * lam + c0;
        float fp = (4.f * lam2 + 2.f * c2) * lam + c1;
        lam -= __fdividef(f, fmaxf(fp, 1e-20f));
    }

    // ---- eigenvector = column of adj(M), M = N - lam I (rank-3, sym) ----
    const float m00 = n00 - lam, m11 = n11 - lam;
    const float m22 = n22 - lam, m33 = n33 - lam;

    const float s0 = m00*m11 - n01*n01;
    const float s1 = m00*n12 - n01*n02;
    const float s2 = m00*n13 - n01*n03;
    const float s3 = n01*n12 - m11*n02;
    const float s4 = n01*n13 - m11*n03;
    const float s5 = n02*n13 - n12*n03;
    const float c5_ = m22*m33 - n23*n23;
    const float c4_ = n12*m33 - n13*n23;
    const float c3_ = n12*n23 - n13*m22;
    const float c2_ = n02*m33 - n03*n23;
    const float c1_ = n02*n23 - n03*m22;

    const float b00 =  m11*c5_ - n12*c4_ + n13*c3_;
    const float b01 = -n01*c5_ + n02*c4_ - n03*c3_;
    const float b02 =  n13*s5  - n23*s4  + m33*s3;
    const float b03 = -n12*s5  + m22*s4  - n23*s3;
    const float b11 =  m00*c5_ - n02*c2_ + n03*c1_;
    const float b12 = -n03*s5  + n23*s2  - m33*s1;
    const float b13 =  n02*s5  - m22*s2  + n23*s1;
    const float b22 =  n03*s4  - n13*s2  + m33*s0;
    const float b23 = -n02*s4  + n12*s2  - n23*s0;
    const float b33 =  n02*s3  - n12*s1  + m22*s0;

    float best = fabsf(b00);
    float qw = b00, qx = b01, qy = b02, qz = b03;
    if (fabsf(b11) > best) { best = fabsf(b11); qw = b01; qx = b11; qy = b12; qz = b13; }
    if (fabsf(b22) > best) { best = fabsf(b22); qw = b02; qx = b12; qy = b22; qz = b23; }
    if (fabsf(b33) > best) { best = fabsf(b33); qw = b03; qx = b13; qy = b23; qz = b33; }

    // ---- unnormalized quaternion -> M = k * Rn, k = lam/(var1*|q|^2) ----
    const float xx = qx*qx, yy = qy*qy, zz = qz*qz, ww = qw*qw;
    const float q2 = ww + xx + yy + zz;
    const float xy = qx*qy, xz = qx*qz, yz = qy*qz;
    const float wx = qw*qx, wy = qw*qy, wz = qw*qz;

    const float k  = __fdividef(lam, var1 * q2);
    const float k2 = 2.f * k;
    const float M00 = k*(ww + xx - yy - zz), M01 = k2*(xy - wz), M02 = k2*(xz + wy);
    const float M10 = k2*(xy + wz), M11 = k*(ww - xx + yy - zz), M12 = k2*(yz - wx);
    const float M20 = k2*(xz - wy), M21 = k2*(yz + wx), M22 = k*(ww - xx - yy + zz);

    const float cx = mbx - (M00*max_ + M01*may_ + M02*maz_);
    const float cy = mby - (M10*max_ + M11*may_ + M12*maz_);
    const float cz = mbz - (M20*max_ + M21*may_ + M22*maz_);

    float acc = 0.f;
    #pragma unroll
    for (int c = 0; c < 7; c++) {
        float2 a0 = P2[3*c], a1 = P2[3*c+1], a2 = P2[3*c+2];
        float2 b0 = G2[3*c], b1 = G2[3*c+1], b2 = G2[3*c+2];
        {
            float ax = a0.x, ay = a0.y, az = a1.x;
            float ex = (M00*ax + M01*ay + M02*az + cx) - b0.x;
            float ey = (M10*ax + M11*ay + M12*az + cy) - b0.y;
            float ez = (M20*ax + M21*ay + M22*az + cz) - b1.x;
            float d2 = ex*ex + ey*ey + ez*ez;
            acc += d2 * rsqrtf(fmaxf(d2, 1e-24f));
        }
        {
            float ax = a1.y, ay = a2.x, az = a2.y;
            float ex = (M00*ax + M01*ay + M02*az + cx) - b1.y;
            float ey = (M10*ax + M11*ay + M12*az + cy) - b2.x;
            float ez = (M20*ax + M21*ay + M22*az + cz) - b2.y;
            float d2 = ex*ex + ey*ey + ez*ez;
            acc += d2 * rsqrtf(fmaxf(d2, 1e-24f));
        }
    }
    return acc * invJ;
}

__global__ void __launch_bounds__(TPB, 3)
pampjpe_kernel(const float* __restrict__ pred,
               const float* __restrict__ gt,
               float* __restrict__ out, int B)
{
    extern __shared__ float smem[];
    const int tid  = threadIdx.x;
    const int warp = tid >> 5;
    const int lane = tid & 31;
    const long long total = (long long)B * FPE;
    const int ntiles = (B + EPT - 1) / EPT;

    const uint32_t sbase = smem_u32(smem);
    const uint32_t mbar_base = sbase + DATA_BYTES;
    // per-warp, per-buffer mbarriers
    const uint32_t mbar0 = mbar_base + (warp * 2 + 0) * 8;
    const uint32_t mbar1 = mbar_base + (warp * 2 + 1) * 8;

    if (tid < WARPS * 2) mbar_init(mbar_base + tid * 8, 1);
    __syncthreads();

    const uint32_t w0 = sbase + warp * WBYTES;
    const uint32_t wreg0 = w0;
    const uint32_t wreg1 = w0 + (uint32_t)TILE_BYTES;
    const float* wptr0 = smem + (warp * WBYTES) / 4;
    const float* wptr1 = smem + (TILE_BYTES + warp * WBYTES) / 4;

    int tile = blockIdx.x;
    if (tile >= ntiles) return;

    // prime the pipeline
    {
        long long fbase = ((long long)tile * EPT + warp * EPW) * FPE;
        prefetch_slice(wreg0, mbar0, pred, gt, fbase, total, lane);
    }

    int buf = 0;
    uint32_t ph0 = 0, ph1 = 0;
    for (; tile < ntiles; tile += GRID) {
        int next = tile + GRID;
        if (next < ntiles) {
            long long fn = ((long long)next * EPT + warp * EPW) * FPE;
            prefetch_slice(buf ? wreg0 : wreg1, buf ? mbar0 : mbar1,
                           pred, gt, fn, total, lane);
        }

        // wait for current buffer (recompute slice shape deterministically)
        long long fbase = ((long long)tile * EPT + warp * EPW) * FPE;
        bool full = (fbase + WF <= total);
        if (full) {
            if (buf == 0) { mbar_wait(mbar0, ph0); ph0 ^= 1; }
            else          { mbar_wait(mbar1, ph1); ph1 ^= 1; }
        } else if (fbase < total) {
            uint32_t rem_bytes = (uint32_t)(total - fbase) * 4u;
            uint32_t b16 = rem_bytes & ~15u;
            if (b16) {
                if (buf == 0) { mbar_wait(mbar0, ph0); ph0 ^= 1; }
                else          { mbar_wait(mbar1, ph1); ph1 ^= 1; }
            }
            if (b16 != rem_bytes && lane == 0) cp_wait0();
        }
        __syncwarp();

        long long elem = (long long)tile * EPT + warp * EPW + lane;
        if (lane < EPW && elem < B) {
            const float* pw = buf ? wptr1 : wptr0;
            const float* gw = pw + WB_ARR / 4;
            out[elem] = compute_elem(pw, gw, lane);
        }
        __syncwarp();   // all lanes done reading before next overwrite
        buf ^= 1;
    }
}

extern "C" void kernel_launch(void* const* d_in, const int* in_sizes, int n_in,
                              void* d_out, int out_size)
{
    const float* pred = (const float*)d_in[0];
    const float* gt   = (const float*)d_in[1];
    float* out = (float*)d_out;
    const int B = out_size;
    const int ntiles = (B + EPT - 1) / EPT;
    const int grid = GRID < ntiles ? GRID : ntiles;

    static bool attr_set = false;
    if (!attr_set) {
        cudaFuncSetAttribute(pampjpe_kernel,
                             cudaFuncAttributeMaxDynamicSharedMemorySize,
                             SMEM_BYTES);
        attr_set = true;
    }
    pampjpe_kernel<<<grid, TPB, SMEM_BYTES>>>(pred, gt, out, B);
}